// round 10
// baseline (speedup 1.0000x reference)
#include <cuda_runtime.h>

// Bilateral filter: B=8, C=3, H=W=512, K=5, sigma_s=2.0, sigma_r=0.1
//
// R10: R9 (4x4 patch/thread, 294 shared-exp pairs, baked log2-spatial
// immediates, 64-thr CTAs, 16 CTAs/SM) + batched reciprocal epilogue:
// the 16 __fdividef RCPs (16x8 = 128 MUFU cyc/warp, 5% of the saturated
// MUFU budget) become 2 RCPs via product-tree inversion; the 1/C1
// un-scale folds into R. MUFU demand 2480 -> 2368 cyc/warp.

#define HW   512
#define TILE 32
#define SROW 36
#define C1F  8.4932165750422091f
#define LSOF(dsq) (-0.18033688011112043f * (float)(dsq))   // log2(exp(-dsq/8))

__device__ __forceinline__ float ex2a(float v) {
    float y;
    asm("ex2.approx.ftz.f32 %0, %1;" : "=f"(y) : "f"(v));
    return y;
}

__device__ __forceinline__ float rcpa(float v) {
    float y;
    asm("rcp.approx.ftz.f32 %0, %1;" : "=f"(y) : "f"(v));
    return y;
}

__device__ __forceinline__ int reflect512(int g) {
    g = (g < 0) ? -g : g;
    return (g > 511) ? (1022 - g) : g;
}

// ownership of a window-local coordinate (window is 8x8, owned core is 2..5)
#define OWN(rr,cc) ((rr) >= 2 && (rr) <= 5 && (cc) >= 2 && (cc) <= 5)

// one unordered pair; all index args compile-time constants after unrolling
#define PAIR(va, vb, ra, ca, rb, cb, di, dj) do {                              \
    const bool oa_ = OWN(ra, ca), ob_ = OWN(rb, cb);                           \
    if (oa_ || ob_) {                                                          \
        float t_ = (va) - (vb);                                                \
        float w_ = ex2a(fmaf(t_, -t_, LSOF((di)*(di)+(dj)*(dj))));             \
        if (oa_) { const int ia_ = ((ra)-2)*4 + ((ca)-2);                      \
                   wsum[ia_] += w_; acc[ia_] = fmaf(w_, (vb), acc[ia_]); }     \
        if (ob_) { const int ib_ = ((rb)-2)*4 + ((cb)-2);                      \
                   wsum[ib_] += w_; acc[ib_] = fmaf(w_, (va), acc[ib_]); }     \
    }                                                                          \
} while (0)

__global__ __launch_bounds__(64, 16)
void bilateral_kernel(const float* __restrict__ x,
                      float* __restrict__ out) {
    __shared__ float tile[36 * SROW];

    const int bx = blockIdx.x * TILE;
    const int by = blockIdx.y * TILE;
    const float* __restrict__ src = x   + (size_t)blockIdx.z * (HW * HW);
    float* __restrict__       dst = out + (size_t)blockIdx.z * (HW * HW);

    const int tid = threadIdx.x;          // 0..63

    const bool interior = (bx != 0) && (bx != HW - TILE) &&
                          (by != 0) && (by != HW - TILE);

    if (interior) {
        const float* base = src + (size_t)(by - 2) * HW + (bx - 2);
        const int c5 = tid & 31;
        const int r2 = tid >> 5;          // 0..1
        #pragma unroll
        for (int it = 0; it < 18; it++) {
            const int r = it * 2 + r2;
            tile[r * SROW + c5] = base[r * HW + c5] * C1F;
        }
        #pragma unroll
        for (int it = 0; it < 3; it++) {
            const int idx = it * 64 + tid;
            if (idx < 144) {
                const int r = idx >> 2;
                const int c = 32 + (idx & 3);
                tile[r * SROW + c] = base[r * HW + c] * C1F;
            }
        }
    } else {
        for (int i = tid; i < 36 * 36; i += 64) {
            const int r = i / 36;
            const int c = i - r * 36;
            tile[r * SROW + c] = src[reflect512(by + r - 2) * HW +
                                     reflect512(bx + c - 2)] * C1F;
        }
    }
    __syncthreads();

    const int R0 = 4 * (tid >> 3);   // smem row of window origin (0..28)
    const int C0 = 4 * (tid & 7);    // smem col of window origin (0..28)

    float wsum[16], acc[16];
    #pragma unroll
    for (int i = 0; i < 16; i++) { wsum[i] = 0.0f; acc[i] = 0.0f; }

    float rows[2][8];   // 2-row ping-pong ring (constant indices after unroll)

    #pragma unroll
    for (int r = 0; r < 8; r++) {
        const int cr = r & 1;

        // load window row r: cols C0..C0+7, two aligned float4 (conflict-free)
        {
            float4 a = *(const float4*)&tile[(R0 + r) * SROW + C0];
            float4 b = *(const float4*)&tile[(R0 + r) * SROW + C0 + 4];
            rows[cr][0] = a.x; rows[cr][1] = a.y;
            rows[cr][2] = a.z; rows[cr][3] = a.w;
            rows[cr][4] = b.x; rows[cr][5] = b.y;
            rows[cr][6] = b.z; rows[cr][7] = b.w;
        }

        // ---- center taps: weight is exactly 1.0, no exp
        if (r >= 2 && r <= 5) {
            #pragma unroll
            for (int c = 2; c <= 5; c++) {
                const int ia = (r - 2) * 4 + (c - 2);
                wsum[ia] += 1.0f;
                acc[ia]  += rows[cr][c];
            }
        }

        // ---- di=0 pairs (within row r)
        if (r >= 2 && r <= 5) {
            #pragma unroll
            for (int c = 1; c <= 5; c++)       // dj = 1
                PAIR(rows[cr][c], rows[cr][c+1], r, c, r, c+1, 0, 1);
            #pragma unroll
            for (int c = 0; c <= 5; c++)       // dj = 2
                PAIR(rows[cr][c], rows[cr][c+2], r, c, r, c+2, 0, 2);
        }

        // ---- di=1 pairs: rows (r-1, r) from the ring
        if (r >= 1) {
            const int pr = (r - 1) & 1;
            #pragma unroll
            for (int dj = -2; dj <= 2; dj++) {
                #pragma unroll
                for (int c = 0; c < 8; c++) {
                    const int cb = c + dj;
                    if (cb < 0 || cb > 7) continue;
                    PAIR(rows[pr][c], rows[cr][cb], r-1, c, r, cb, 1, dj);
                }
            }
        }

        // ---- di=2 pairs: partner row r-2 re-read from smem (transient regs)
        if (r >= 2) {
            float p2[8];
            {
                float4 a = *(const float4*)&tile[(R0 + r - 2) * SROW + C0];
                float4 b = *(const float4*)&tile[(R0 + r - 2) * SROW + C0 + 4];
                p2[0] = a.x; p2[1] = a.y; p2[2] = a.z; p2[3] = a.w;
                p2[4] = b.x; p2[5] = b.y; p2[6] = b.z; p2[7] = b.w;
            }
            #pragma unroll
            for (int dj = -2; dj <= 2; dj++) {
                #pragma unroll
                for (int c = 0; c < 8; c++) {
                    const int cb = c + dj;
                    if (cb < 0 || cb > 7) continue;
                    PAIR(p2[c], rows[cr][cb], r-2, c, r, cb, 2, dj);
                }
            }
        }
    }

    // ---- normalize: batched reciprocal (1 RCP per 8 pixels, 2 total).
    // inv_i = (1/C1) / wsum_i via product tree; wsum in [1, ~14.2] so the
    // 8-way product <= 14.2^8 ~ 1.6e9 (safe in fp32).
    const float INV = 1.0f / C1F;
    float invw[16];
    #pragma unroll
    for (int g = 0; g < 2; g++) {
        const float* w = wsum + g * 8;
        float* iw = invw + g * 8;
        float p01 = w[0] * w[1], p23 = w[2] * w[3];
        float p45 = w[4] * w[5], p67 = w[6] * w[7];
        float p0123 = p01 * p23, p4567 = p45 * p67;
        float R = rcpa(p0123 * p4567) * INV;
        float r0123 = R * p4567, r4567 = R * p0123;
        float r01 = r0123 * p23, r23 = r0123 * p01;
        float r45 = r4567 * p67, r67 = r4567 * p45;
        iw[0] = r01 * w[1];  iw[1] = r01 * w[0];
        iw[2] = r23 * w[3];  iw[3] = r23 * w[2];
        iw[4] = r45 * w[5];  iw[5] = r45 * w[4];
        iw[6] = r67 * w[7];  iw[7] = r67 * w[6];
    }

    #pragma unroll
    for (int pr = 0; pr < 4; pr++) {
        float4 o;
        o.x = acc[pr*4 + 0] * invw[pr*4 + 0];
        o.y = acc[pr*4 + 1] * invw[pr*4 + 1];
        o.z = acc[pr*4 + 2] * invw[pr*4 + 2];
        o.w = acc[pr*4 + 3] * invw[pr*4 + 3];
        *(float4*)&dst[(by + R0 + pr) * HW + bx + C0] = o;
    }
}

extern "C" void kernel_launch(void* const* d_in, const int* in_sizes, int n_in,
                              void* d_out, int out_size) {
    const float* x = (const float*)d_in[0];  // (8,3,512,512)
    float* out     = (float*)d_out;

    dim3 block(64);
    dim3 grid(HW / TILE, HW / TILE, 24);   // 16 x 16 x 24 = 6144 CTAs
    bilateral_kernel<<<grid, block>>>(x, out);
}